// round 1
// baseline (speedup 1.0000x reference)
#include <cuda_runtime.h>
#include <math.h>

#define Bn   256
#define Cn   112
#define C2   224
#define Pn   200
#define Dn   10
#define NCLSn 200
#define MAXD 256.0f
#define EPSV 1e-8f

// ---------------- device scratch (fully rewritten every launch) -------------
__device__ unsigned long long g_mask[C2][4];   // top-10 set bitmask per row
__device__ float g_part_op[Cn];                // ortho_p partial per c
__device__ float g_part_oc[Cn];                // ortho_c partial per c
__device__ float g_part_ent[Cn];               // BCE column sums
__device__ float g_clst[Bn];
__device__ float g_sep[Bn];
__device__ float g_tl[Bn];

// ---------------------------------------------------------------------------
// warp-synchronous top-10 selection over 200 values (matches lax.top_k
// tie-break: equal values -> lower index wins). Writes bitmask for row r.
__device__ __forceinline__ void topk10_row(const float* s, int r) {
    int lane = threadIdx.x & 31;
    float val[7];
    #pragma unroll
    for (int k = 0; k < 7; k++) {
        int p = lane + 32 * k;
        val[k] = (p < Pn) ? s[p] : -1e30f;
    }
    unsigned used = 0;
    unsigned long long mask[4] = {0ull, 0ull, 0ull, 0ull};
    #pragma unroll
    for (int it = 0; it < 10; it++) {
        float bv = -1e30f; int bi = 1 << 30;
        #pragma unroll
        for (int k = 0; k < 7; k++) {
            if (!((used >> k) & 1u)) {
                float x = val[k]; int p = lane + 32 * k;
                if (x > bv || (x == bv && p < bi)) { bv = x; bi = p; }
            }
        }
        #pragma unroll
        for (int off = 16; off; off >>= 1) {
            float ov = __shfl_down_sync(0xffffffffu, bv, off);
            int   oi = __shfl_down_sync(0xffffffffu, bi, off);
            if (ov > bv || (ov == bv && oi < bi)) { bv = ov; bi = oi; }
        }
        bi = __shfl_sync(0xffffffffu, bi, 0);
        if ((bi & 31) == lane) used |= 1u << (bi >> 5);
        if (lane == 0) mask[bi >> 6] |= 1ull << (bi & 63);
    }
    if (lane == 0) {
        #pragma unroll
        for (int w = 0; w < 4; w++) g_mask[r][w] = mask[w];
    }
}

// ---------------------------------------------------------------------------
// K1: one block per concept c (112 blocks, 256 threads).
//   - loads proto rows c and c+C to smem
//   - row-sums + top-10 masks for both rows
//   - norms, self-grams, cross-gram -> ortho partials
//   - BCE column sum for column c -> concepts_loss[c] + entropy partial
__global__ __launch_bounds__(256) void k1(const float* __restrict__ proto,
                                          const float* __restrict__ cx,
                                          const float* __restrict__ cy,
                                          float* __restrict__ out) {
    __shared__ float rA[Pn * Dn];
    __shared__ float rB[Pn * Dn];
    __shared__ float sA[Pn], sB[Pn];
    __shared__ float nA[Dn], nB[Dn];
    __shared__ float cpv[128], ccv[128];
    __shared__ float red[256];

    const int c = blockIdx.x;
    const int t = threadIdx.x;

    const float* pA = proto + (size_t)c * Pn * Dn;
    const float* pB = proto + (size_t)(c + Cn) * Pn * Dn;
    for (int i = t; i < Pn * Dn; i += 256) { rA[i] = pA[i]; rB[i] = pB[i]; }

    // BCE element for (b=t, c): independent global loads
    float x = cx[t * Cn + c];
    float y = cy[t * Cn + c];
    float bce = fmaxf(x, 0.0f) + log1pf(expf(-fabsf(x))) - x * y;

    __syncthreads();

    // row sums (threads 0..199) and column norms (threads 200..219)
    if (t < Pn) {
        float a = 0.f, b = 0.f;
        #pragma unroll
        for (int d = 0; d < Dn; d++) { a += rA[t * Dn + d]; b += rB[t * Dn + d]; }
        sA[t] = a; sB[t] = b;
    } else if (t < Pn + 2 * Dn) {
        int u = t - Pn; int which = u / Dn; int d = u % Dn;
        const float* r = which ? rB : rA;
        float s = 0.f;
        for (int p = 0; p < Pn; p++) { float v = r[p * Dn + d]; s += v * v; }
        if (which) nB[d] = sqrtf(s); else nA[d] = sqrtf(s);
    }
    __syncthreads();

    // phase 3: topk (warps 0,1) + grams (threads 64..163) run concurrently
    int w = t >> 5;
    if (w == 0) {
        topk10_row(sA, c);
    } else if (w == 1) {
        topk10_row(sB, c + Cn);
    }
    if (t >= 64 && t < 164) {
        int q = t - 64, i = q / Dn, j = q % Dn;
        float gp = 0.f, gn = 0.f, gc = 0.f;
        for (int p = 0; p < Pn; p++) {
            float ai = rA[p * Dn + i], aj = rA[p * Dn + j];
            float bi = rB[p * Dn + i], bj = rB[p * Dn + j];
            gp += ai * aj;
            gn += bi * bj;
            gc += aj * bi;          // Gc[c,i,j] = sum_p pos[c,p,j]*neg[c,p,i]
        }
        cpv[q] = gp / fmaxf(nA[i] * nA[j], EPSV) + gn / fmaxf(nB[i] * nB[j], EPSV);
        ccv[q] = gc / fmaxf(nB[i] * nA[j], EPSV);   // denom nneg[i]*npos[j]
    }
    if (t >= 164 && t < 192) { cpv[t - 64] = 0.f; ccv[t - 64] = 0.f; }
    red[t] = bce;
    __syncthreads();

    // reduce BCE (256)
    #pragma unroll
    for (int s = 128; s > 0; s >>= 1) {
        if (t < s) red[t] += red[t + s];
        __syncthreads();
    }
    if (t == 0) { out[1 + c] = red[0] / (float)Bn; g_part_ent[c] = red[0]; }

    // reduce gram contributions (128)
    #pragma unroll
    for (int s = 64; s > 0; s >>= 1) {
        if (t < s) { cpv[t] += cpv[t + s]; ccv[t] += ccv[t + s]; }
        __syncthreads();
    }
    if (t == 0) { g_part_op[c] = cpv[0]; g_part_oc[c] = ccv[0]; }
}

// ---------------------------------------------------------------------------
// K2: one block per batch b (256 blocks, 128 threads).
//   - target-loss (log-softmax over 200) for row b
//   - clst/sep partial: per c, min over top-k set / complement of min_d[b,:]
__global__ __launch_bounds__(128) void k2(const float* __restrict__ mind,
                                          const float* __restrict__ cy,
                                          const float* __restrict__ tlog,
                                          const int* __restrict__ tt) {
    __shared__ float md[Pn];
    __shared__ float red[128];
    const int b = blockIdx.x;
    const int t = threadIdx.x;

    for (int i = t; i < Pn; i += 128) md[i] = mind[b * Pn + i];

    // ---- target loss for row b ----
    float l0 = tlog[b * NCLSn + t];
    float l1v = (t < NCLSn - 128) ? tlog[b * NCLSn + 128 + t] : -1e30f;
    red[t] = fmaxf(l0, l1v);
    __syncthreads();
    #pragma unroll
    for (int s = 64; s > 0; s >>= 1) {
        if (t < s) red[t] = fmaxf(red[t], red[t + s]);
        __syncthreads();
    }
    float mx = red[0];
    __syncthreads();
    float se = expf(l0 - mx) + ((t < NCLSn - 128) ? expf(l1v - mx) : 0.f);
    red[t] = se;
    __syncthreads();
    #pragma unroll
    for (int s = 64; s > 0; s >>= 1) {
        if (t < s) red[t] += red[t + s];
        __syncthreads();
    }
    if (t == 0) {
        int tti = tt[b];
        g_tl[b] = -(tlog[b * NCLSn + tti] - mx - logf(red[0]));
    }
    __syncthreads();

    // ---- clst/sep min-scans ----
    float m1s = 0.f, m2s = 0.f;
    if (t < Cn) {
        float yv = cy[b * Cn + t];
        int r1 = (yv > 0.5f) ? t : t + Cn;        // row for clst (idx)
        int r2 = (yv > 0.5f) ? t + Cn : t;        // row for sep  (inv_idx)
        float m1v = 1e30f, m2v = 1e30f;
        #pragma unroll
        for (int wdi = 0; wdi < 4; wdi++) {
            unsigned long long aw = g_mask[r1][wdi];
            unsigned long long bw = ~g_mask[r2][wdi];
            if (wdi == 3) bw &= 0xFFull;          // bits 192..199 only
            int base = wdi * 64;
            while (aw) {
                int k = __ffsll((long long)aw) - 1;
                m1v = fminf(m1v, md[base + k]);
                aw &= aw - 1;
            }
            while (bw) {
                int k = __ffsll((long long)bw) - 1;
                m2v = fminf(m2v, md[base + k]);
                bw &= bw - 1;
            }
        }
        m1s = m1v; m2s = m2v;
    }
    red[t] = m1s;
    __syncthreads();
    #pragma unroll
    for (int s = 64; s > 0; s >>= 1) {
        if (t < s) red[t] += red[t + s];
        __syncthreads();
    }
    if (t == 0) g_clst[b] = red[0];
    __syncthreads();
    red[t] = m2s;
    __syncthreads();
    #pragma unroll
    for (int s = 64; s > 0; s >>= 1) {
        if (t < s) red[t] += red[t + s];
        __syncthreads();
    }
    if (t == 0) g_sep[b] = red[0];
}

// ---------------------------------------------------------------------------
// K3: single block, 256 threads. l1 sum + all final reductions + scalars.
__device__ __forceinline__ float block_sum256(float v, float* red, int t) {
    red[t] = v;
    __syncthreads();
    #pragma unroll
    for (int s = 128; s > 0; s >>= 1) {
        if (t < s) red[t] += red[t + s];
        __syncthreads();
    }
    float r = red[0];
    __syncthreads();
    return r;
}

__global__ __launch_bounds__(256) void k3(const float* __restrict__ wgt,
                                          const float* __restrict__ msk,
                                          float* __restrict__ out) {
    __shared__ float red[256];
    const int t = threadIdx.x;

    float l1p = 0.f;
    for (int i = t; i < C2 * Pn; i += 256) l1p += fabsf(wgt[i] * msk[i]);

    float l1   = block_sum256(l1p, red, t);
    float tls  = block_sum256(g_tl[t], red, t);
    float cls  = block_sum256(g_clst[t], red, t);
    float sps  = block_sum256(g_sep[t], red, t);
    float ents = block_sum256((t < Cn) ? g_part_ent[t] : 0.f, red, t);
    float ops  = block_sum256((t < Cn) ? g_part_op[t] : 0.f, red, t);
    float ocs  = block_sum256((t < Cn) ? g_part_oc[t] : 0.f, red, t);

    if (t == 0) {
        float target_loss = tls / (float)Bn;
        float entropy     = ents / (float)(Bn * Cn);
        float clst        = cls / (float)(Bn * Cn);
        float sep         = sps / (float)(Bn * Cn);
        float ortho_p     = ops / (float)(Dn * Cn * 2) - 1.0f;
        float ortho_c     = ocs / (float)(Dn * Cn);
        float summed = 1.0f * entropy + 0.8f * clst + (-0.08f) * sep
                     + 1e-4f * l1 + 1.0f * ortho_p + 1.0f * ortho_c;
        float total = target_loss + summed;
        out[0]   = target_loss;
        out[113] = summed;
        out[114] = total;
        out[115] = entropy;
        out[116] = clst;
        out[117] = sep;
        out[118] = l1;
        out[119] = ortho_p;
        out[120] = ortho_c;
    }
}

// ---------------------------------------------------------------------------
extern "C" void kernel_launch(void* const* d_in, const int* in_sizes, int n_in,
                              void* d_out, int out_size) {
    const float* cx    = (const float*)d_in[0];  // concepts_pred_logits (B,C)
    const float* cy    = (const float*)d_in[1];  // concepts_true        (B,C)
    const float* mind  = (const float*)d_in[2];  // min_distances        (B,P)
    const float* proto = (const float*)d_in[3];  // proto_presence       (2C,P,D)
    const float* tlog  = (const float*)d_in[4];  // target_pred_logits   (B,NCLS)
    const int*   tt    = (const int*)d_in[5];    // target_true          (B,)
    const float* wgt   = (const float*)d_in[6];  // last_layer_weight    (2C,P)
    const float* msk   = (const float*)d_in[7];  // l1_mask              (2C,P)
    float* out = (float*)d_out;

    k1<<<Cn, 256>>>(proto, cx, cy, out);
    k2<<<Bn, 128>>>(mind, cy, tlog, tt);
    k3<<<1, 256>>>(wgt, msk, out);
}

// round 2
// speedup vs baseline: 1.6623x; 1.6623x over previous
#include <cuda_runtime.h>
#include <math.h>

#define Bn    256
#define Cn    112
#define C2    224
#define Pn    200
#define Dn    10
#define NCLSn 200
#define MAXD  256.0f
#define EPSV  1e-8f

// ---------------- device scratch (fully rewritten every launch) -------------
__device__ unsigned long long g_mask[C2][4];   // top-10 set bitmask per row
__device__ int   g_idx[C2][10];                // top-10 index list per row
__device__ float g_part_op[Cn];
__device__ float g_part_oc[Cn];
__device__ float g_part_ent[Cn];
__device__ float g_clst[Bn];
__device__ float g_sep[Bn];
__device__ float g_tl[Bn];
__device__ float g_l1[Bn];

// ---------------------------------------------------------------------------
// warp top-10 (largest, ties -> lower index) over 200 smem values.
__device__ __forceinline__ void topk10_row(const float* s, int r) {
    int lane = threadIdx.x & 31;
    float val[7];
    #pragma unroll
    for (int k = 0; k < 7; k++) {
        int p = lane + 32 * k;
        val[k] = (p < Pn) ? s[p] : -1e30f;
    }
    unsigned used = 0;
    unsigned long long mask[4] = {0ull, 0ull, 0ull, 0ull};
    #pragma unroll
    for (int it = 0; it < 10; it++) {
        float bv = -1e30f; int bi = 1 << 30;
        #pragma unroll
        for (int k = 0; k < 7; k++) {
            if (!((used >> k) & 1u)) {
                float x = val[k]; int p = lane + 32 * k;
                if (x > bv || (x == bv && p < bi)) { bv = x; bi = p; }
            }
        }
        #pragma unroll
        for (int off = 16; off; off >>= 1) {
            float ov = __shfl_down_sync(0xffffffffu, bv, off);
            int   oi = __shfl_down_sync(0xffffffffu, bi, off);
            if (ov > bv || (ov == bv && oi < bi)) { bv = ov; bi = oi; }
        }
        bi = __shfl_sync(0xffffffffu, bi, 0);
        if ((bi & 31) == lane) used |= 1u << (bi >> 5);
        if (lane == 0) { mask[bi >> 6] |= 1ull << (bi & 63); g_idx[r][it] = bi; }
    }
    if (lane == 0) {
        #pragma unroll
        for (int w = 0; w < 4; w++) g_mask[r][w] = mask[w];
    }
}

// block sum: result valid at t==0 only.
template <int NT>
__device__ __forceinline__ float bsum(float v, float* s, int t) {
    #pragma unroll
    for (int off = 16; off; off >>= 1) v += __shfl_down_sync(0xffffffffu, v, off);
    __syncthreads();
    if ((t & 31) == 0) s[t >> 5] = v;
    __syncthreads();
    float r = 0.f;
    if (t == 0) {
        #pragma unroll
        for (int w = 0; w < NT / 32; w++) r += s[w];
    }
    return r;
}

// ---------------------------------------------------------------------------
// K1: one block per concept c (112 blocks, 256 threads).
__global__ __launch_bounds__(256) void k1(const float* __restrict__ proto,
                                          const float* __restrict__ cx,
                                          const float* __restrict__ cy,
                                          float* __restrict__ out) {
    __shared__ float rA[Pn * Dn];
    __shared__ float rB[Pn * Dn];
    __shared__ float sA[Pn], sB[Pn];
    __shared__ float part[200];
    __shared__ float invn[2][Dn];
    __shared__ float red[8];

    const int c = blockIdx.x;
    const int t = threadIdx.x;

    const float4* pA = (const float4*)(proto + (size_t)c * Pn * Dn);
    const float4* pB = (const float4*)(proto + (size_t)(c + Cn) * Pn * Dn);
    for (int i = t; i < (Pn * Dn) / 4; i += 256) {
        ((float4*)rA)[i] = pA[i];
        ((float4*)rB)[i] = pB[i];
    }

    // BCE element for (b=t, c)
    float x = cx[t * Cn + c];
    float y = cy[t * Cn + c];
    float bce = fmaxf(x, 0.0f) + log1pf(expf(-fabsf(x))) - x * y;

    __syncthreads();

    // row sums (for topk) + column-norm partials, same phase
    if (t < Pn) {
        float a = 0.f, b = 0.f;
        #pragma unroll
        for (int d = 0; d < Dn; d++) { a += rA[t * Dn + d]; b += rB[t * Dn + d]; }
        sA[t] = a; sB[t] = b;

        int which = t / 100, rem = t % 100;
        int d = rem / 10, seg = rem % 10;
        const float* r = which ? rB : rA;
        float s = 0.f;
        #pragma unroll
        for (int p = seg * 20; p < seg * 20 + 20; p++) {
            float v = r[p * Dn + d]; s += v * v;
        }
        part[t] = s;
    }
    __syncthreads();
    if (t < 20) {
        int which = t / 10, d = t % 10;
        float s = 0.f;
        #pragma unroll
        for (int seg = 0; seg < 10; seg++) s += part[which * 100 + d * 10 + seg];
        invn[which][d] = rsqrtf(fmaxf(s, EPSV * EPSV));
    }
    __syncthreads();

    // topk (warps 0,1) concurrent with normalized-column-sum accumulation
    int w = t >> 5;
    if (w == 0)      topk10_row(sA, c);
    else if (w == 1) topk10_row(sB, c + Cn);

    float aop = 0.f, aoc = 0.f;
    if (t >= 64) {
        for (int p = t - 64; p < Pn; p += 192) {
            float ua = 0.f, ub = 0.f;
            #pragma unroll
            for (int d = 0; d < Dn; d++) {
                ua += rA[p * Dn + d] * invn[0][d];
                ub += rB[p * Dn + d] * invn[1][d];
            }
            aop += ua * ua + ub * ub;
            aoc += ua * ub;
        }
    }

    float sb = bsum<256>(bce, red, t);
    if (t == 0) { out[1 + c] = sb / (float)Bn; g_part_ent[c] = sb; }
    float so = bsum<256>(aop, red, t);
    if (t == 0) g_part_op[c] = so;
    float sc = bsum<256>(aoc, red, t);
    if (t == 0) g_part_oc[c] = sc;
}

// ---------------------------------------------------------------------------
// K2: one block per batch b (256 blocks, 128 threads).
__global__ __launch_bounds__(128) void k2(const float* __restrict__ mind,
                                          const float* __restrict__ cy,
                                          const float* __restrict__ tlog,
                                          const int* __restrict__ tt,
                                          const float* __restrict__ wgt,
                                          const float* __restrict__ msk) {
    __shared__ float md[Pn];
    __shared__ float red[128];
    __shared__ int cand[11];
    const int b = blockIdx.x;
    const int t = threadIdx.x;

    for (int i = t; i < Pn; i += 128) md[i] = mind[b * Pn + i];

    // ---- target loss (log-softmax) for row b ----
    float l0 = tlog[b * NCLSn + t];
    float l1v = (t < NCLSn - 128) ? tlog[b * NCLSn + 128 + t] : -1e30f;
    red[t] = fmaxf(l0, l1v);
    __syncthreads();
    #pragma unroll
    for (int s = 64; s > 0; s >>= 1) {
        if (t < s) red[t] = fmaxf(red[t], red[t + s]);
        __syncthreads();
    }
    float mx = red[0];
    __syncthreads();
    red[t] = expf(l0 - mx) + ((t < NCLSn - 128) ? expf(l1v - mx) : 0.f);
    __syncthreads();
    #pragma unroll
    for (int s = 64; s > 0; s >>= 1) {
        if (t < s) red[t] += red[t + s];
        __syncthreads();
    }
    if (t == 0) {
        int tti = tt[b];
        g_tl[b] = -(tlog[b * NCLSn + tti] - mx - logf(red[0]));
    }

    // ---- 11 smallest of md (warp 0): complement-min candidates ----
    if (t < 32) {
        float val[7];
        #pragma unroll
        for (int k = 0; k < 7; k++) {
            int p = t + 32 * k;
            val[k] = (p < Pn) ? md[p] : 1e30f;
        }
        unsigned used = 0;
        #pragma unroll
        for (int it = 0; it < 11; it++) {
            float bv = 1e30f; int bi = 1 << 30;
            #pragma unroll
            for (int k = 0; k < 7; k++) {
                if (!((used >> k) & 1u)) {
                    float xv = val[k]; int p = t + 32 * k;
                    if (xv < bv || (xv == bv && p < bi)) { bv = xv; bi = p; }
                }
            }
            #pragma unroll
            for (int off = 16; off; off >>= 1) {
                float ov = __shfl_down_sync(0xffffffffu, bv, off);
                int   oi = __shfl_down_sync(0xffffffffu, bi, off);
                if (ov < bv || (ov == bv && oi < bi)) { bv = ov; bi = oi; }
            }
            bi = __shfl_sync(0xffffffffu, bi, 0);
            if ((bi & 31) == t) used |= 1u << (bi >> 5);
            if (t == 0) cand[it] = bi;
        }
    }
    __syncthreads();

    // ---- clst/sep per concept ----
    float m1s = 0.f, m2s = 0.f;
    if (t < Cn) {
        float yv = cy[b * Cn + t];
        int r1 = (yv > 0.5f) ? t : t + Cn;        // clst row
        int r2 = (yv > 0.5f) ? t + Cn : t;        // sep  row
        float m1 = 1e30f;
        const int* gi = g_idx[r1];
        #pragma unroll
        for (int k = 0; k < 10; k++) m1 = fminf(m1, md[gi[k]]);
        unsigned long long mw0 = g_mask[r2][0], mw1 = g_mask[r2][1];
        unsigned long long mw2 = g_mask[r2][2], mw3 = g_mask[r2][3];
        float m2 = 1e30f;
        #pragma unroll
        for (int k = 0; k < 11; k++) {
            int id = cand[k];
            unsigned long long wsel = (id < 64) ? mw0 : (id < 128) ? mw1 : (id < 192) ? mw2 : mw3;
            if (!((wsel >> (id & 63)) & 1ull)) { m2 = md[id]; break; }
        }
        m1s = m1; m2s = m2;
    }
    __syncthreads();
    red[t] = m1s;
    __syncthreads();
    #pragma unroll
    for (int s = 64; s > 0; s >>= 1) {
        if (t < s) red[t] += red[t + s];
        __syncthreads();
    }
    if (t == 0) g_clst[b] = red[0];
    __syncthreads();
    red[t] = m2s;
    __syncthreads();
    #pragma unroll
    for (int s = 64; s > 0; s >>= 1) {
        if (t < s) red[t] += red[t + s];
        __syncthreads();
    }
    if (t == 0) g_sep[b] = red[0];

    // ---- l1 partial: slice [b*175, (b+1)*175) ----
    float lp = 0.f;
    for (int i = b * 175 + t; i < b * 175 + 175; i += 128)
        lp += fabsf(wgt[i] * msk[i]);
    __syncthreads();
    red[t] = lp;
    __syncthreads();
    #pragma unroll
    for (int s = 64; s > 0; s >>= 1) {
        if (t < s) red[t] += red[t + s];
        __syncthreads();
    }
    if (t == 0) g_l1[b] = red[0];
}

// ---------------------------------------------------------------------------
// K3: single block, final reductions of small partial arrays.
__device__ __forceinline__ float bs256(float v, float* red, int t) {
    __syncthreads();
    red[t] = v;
    __syncthreads();
    #pragma unroll
    for (int s = 128; s > 0; s >>= 1) {
        if (t < s) red[t] += red[t + s];
        __syncthreads();
    }
    return red[0];
}

__global__ __launch_bounds__(256) void k3(float* __restrict__ out) {
    __shared__ float red[256];
    const int t = threadIdx.x;

    float l1   = bs256(g_l1[t], red, t);
    float tls  = bs256(g_tl[t], red, t);
    float cls  = bs256(g_clst[t], red, t);
    float sps  = bs256(g_sep[t], red, t);
    float ents = bs256((t < Cn) ? g_part_ent[t] : 0.f, red, t);
    float ops  = bs256((t < Cn) ? g_part_op[t] : 0.f, red, t);
    float ocs  = bs256((t < Cn) ? g_part_oc[t] : 0.f, red, t);

    if (t == 0) {
        float target_loss = tls / (float)Bn;
        float entropy     = ents / (float)(Bn * Cn);
        float clst        = cls / (float)(Bn * Cn);
        float sep         = sps / (float)(Bn * Cn);
        float ortho_p     = ops / (float)(Dn * Cn * 2) - 1.0f;
        float ortho_c     = ocs / (float)(Dn * Cn);
        float summed = entropy + 0.8f * clst + (-0.08f) * sep
                     + 1e-4f * l1 + ortho_p + ortho_c;
        out[0]   = target_loss;
        out[113] = summed;
        out[114] = target_loss + summed;
        out[115] = entropy;
        out[116] = clst;
        out[117] = sep;
        out[118] = l1;
        out[119] = ortho_p;
        out[120] = ortho_c;
    }
}

// ---------------------------------------------------------------------------
extern "C" void kernel_launch(void* const* d_in, const int* in_sizes, int n_in,
                              void* d_out, int out_size) {
    const float* cx    = (const float*)d_in[0];
    const float* cy    = (const float*)d_in[1];
    const float* mind  = (const float*)d_in[2];
    const float* proto = (const float*)d_in[3];
    const float* tlog  = (const float*)d_in[4];
    const int*   tt    = (const int*)d_in[5];
    const float* wgt   = (const float*)d_in[6];
    const float* msk   = (const float*)d_in[7];
    float* out = (float*)d_out;

    k1<<<Cn, 256>>>(proto, cx, cy, out);
    k2<<<Bn, 128>>>(mind, cy, tlog, tt, wgt, msk);
    k3<<<1, 256>>>(out);
}

// round 4
// speedup vs baseline: 1.9723x; 1.1864x over previous
#include <cuda_runtime.h>
#include <math.h>

#define Bn    256
#define Cn    112
#define C2    224
#define Pn    200
#define Dn    10
#define NCLSn 200

// ---------------- device scratch (fully rewritten every launch) -------------
__device__ unsigned long long g_mask[C2][4];   // top-10 set bitmask per row
__device__ int   g_idx[C2][10];                // top-10 index list per row
__device__ float g_ua[C2 * Pn];                // normalized row-sums per row
__device__ float g_aop[C2];                    // ortho_p partial per row
__device__ float g_oc[Cn];                     // ortho_c partial per c
__device__ float g_part_ent[Cn];               // BCE column sums
__device__ float g_clst[Bn];
__device__ float g_sep[Bn];
__device__ float g_tl[Bn];
__device__ float g_l1[Bn];
__device__ int   g_ctr;

// ---------------------------------------------------------------------------
// warp top-10 (largest, ties -> lower index) over Pn smem values. Warp 0 only.
__device__ __forceinline__ void topk10_row(const float* s, int r) {
    int lane = threadIdx.x & 31;
    float val[7];
    #pragma unroll
    for (int k = 0; k < 7; k++) {
        int p = lane + 32 * k;
        val[k] = (p < Pn) ? s[p] : -1e30f;
    }
    unsigned used = 0;
    unsigned long long mask[4] = {0ull, 0ull, 0ull, 0ull};
    #pragma unroll
    for (int it = 0; it < 10; it++) {
        float bv = -1e30f; int bi = 1 << 30;
        #pragma unroll
        for (int k = 0; k < 7; k++) {
            if (!((used >> k) & 1u)) {
                float x = val[k]; int p = lane + 32 * k;
                if (x > bv || (x == bv && p < bi)) { bv = x; bi = p; }
            }
        }
        #pragma unroll
        for (int off = 16; off; off >>= 1) {
            float ov = __shfl_down_sync(0xffffffffu, bv, off);
            int   oi = __shfl_down_sync(0xffffffffu, bi, off);
            if (ov > bv || (ov == bv && oi < bi)) { bv = ov; bi = oi; }
        }
        bi = __shfl_sync(0xffffffffu, bi, 0);
        if ((bi & 31) == lane) used |= 1u << (bi >> 5);
        if (lane == 0) { mask[bi >> 6] |= 1ull << (bi & 63); g_idx[r][it] = bi; }
    }
    if (lane == 0) {
        #pragma unroll
        for (int w = 0; w < 4; w++) g_mask[r][w] = mask[w];
    }
}

// block sum over 128 threads; every thread gets the total.
__device__ __forceinline__ float bsum128(float v, float* s, int t) {
    #pragma unroll
    for (int off = 16; off; off >>= 1) v += __shfl_down_sync(0xffffffffu, v, off);
    __syncthreads();
    if ((t & 31) == 0) s[t >> 5] = v;
    __syncthreads();
    return s[0] + s[1] + s[2] + s[3];
}

// ---------------------------------------------------------------------------
// kA: 224 blocks (one proto row each) x 128 threads.
__global__ __launch_bounds__(128) void kA(const float* __restrict__ proto) {
    __shared__ float rA[Pn * Dn];   // 8 KB
    __shared__ float sA[Pn];
    __shared__ float part[100];
    __shared__ float invn[Dn];
    __shared__ float redw[4];

    const int r = blockIdx.x;
    const int t = threadIdx.x;

    if (r == 0 && t == 0) g_ctr = 0;   // reset last-block counter for kB

    const float4* pr = (const float4*)(proto + (size_t)r * Pn * Dn);
    #pragma unroll
    for (int i = t; i < (Pn * Dn) / 4; i += 128) ((float4*)rA)[i] = pr[i];
    __syncthreads();

    // row sums (p = t and t+128) + column sq-norm partials (t < 100)
    {
        float a = 0.f;
        #pragma unroll
        for (int d = 0; d < Dn; d++) a += rA[t * Dn + d];
        sA[t] = a;
        int p2 = t + 128;
        if (p2 < Pn) {
            float b = 0.f;
            #pragma unroll
            for (int d = 0; d < Dn; d++) b += rA[p2 * Dn + d];
            sA[p2] = b;
        }
    }
    if (t < 100) {
        int d = t / 10, seg = t % 10;
        float s = 0.f;
        #pragma unroll
        for (int p = seg * 20; p < seg * 20 + 20; p++) {
            float v = rA[p * Dn + d]; s += v * v;
        }
        part[t] = s;
    }
    __syncthreads();
    if (t < Dn) {
        float s = 0.f;
        #pragma unroll
        for (int seg = 0; seg < 10; seg++) s += part[t * 10 + seg];
        invn[t] = rsqrtf(fmaxf(s, 1e-16f));
    }
    __syncthreads();

    // warp 0: topk; warps 1-3: normalized row-sums + ortho_p partial
    float aop = 0.f;
    if (t < 32) {
        topk10_row(sA, r);
    } else {
        for (int p = t - 32; p < Pn; p += 96) {
            float ua = 0.f;
            #pragma unroll
            for (int d = 0; d < Dn; d++) ua += rA[p * Dn + d] * invn[d];
            g_ua[r * Pn + p] = ua;
            aop += ua * ua;
        }
        #pragma unroll
        for (int off = 16; off; off >>= 1)
            aop += __shfl_down_sync(0xffffffffu, aop, off);
        if ((t & 31) == 0) redw[t >> 5] = aop;
    }
    __syncthreads();
    if (t == 0) g_aop[r] = redw[1] + redw[2] + redw[3];
}

// ---------------------------------------------------------------------------
// kB: 368 blocks x 128 threads.
//   blocks 0..255   : per-batch b (softmax, clst/sep, l1 slice)
//   blocks 256..367 : per-concept c (BCE column sum, ortho_c dot)
//   last block done : final scalar reduction
__global__ __launch_bounds__(128) void kB(const float* __restrict__ mind,
                                          const float* __restrict__ cy,
                                          const float* __restrict__ tlog,
                                          const int* __restrict__ tt,
                                          const float* __restrict__ wgt,
                                          const float* __restrict__ msk,
                                          const float* __restrict__ cx,
                                          float* __restrict__ out) {
    __shared__ float md[Pn];
    __shared__ int cand[11];
    __shared__ float sm1[4], sm2[4];
    __shared__ float reds[4];
    __shared__ int amLast;

    const int bid = blockIdx.x;
    const int t = threadIdx.x;
    const int lane = t & 31;
    const int w = t >> 5;

    if (bid < Bn) {
        const int b = bid;
        md[t] = mind[b * Pn + t];
        if (t < Pn - 128) md[t + 128] = mind[b * Pn + 128 + t];
        __syncthreads();

        if (w == 0) {
            // 11 smallest of md -> cand (complement-min candidates)
            float val[7];
            #pragma unroll
            for (int k = 0; k < 7; k++) {
                int p = lane + 32 * k;
                val[k] = (p < Pn) ? md[p] : 1e30f;
            }
            unsigned used = 0;
            #pragma unroll
            for (int it = 0; it < 11; it++) {
                float bv = 1e30f; int bi = 1 << 30;
                #pragma unroll
                for (int k = 0; k < 7; k++) {
                    if (!((used >> k) & 1u)) {
                        float xv = val[k]; int p = lane + 32 * k;
                        if (xv < bv || (xv == bv && p < bi)) { bv = xv; bi = p; }
                    }
                }
                #pragma unroll
                for (int off = 16; off; off >>= 1) {
                    float ov = __shfl_down_sync(0xffffffffu, bv, off);
                    int   oi = __shfl_down_sync(0xffffffffu, bi, off);
                    if (ov < bv || (ov == bv && oi < bi)) { bv = ov; bi = oi; }
                }
                bi = __shfl_sync(0xffffffffu, bi, 0);
                if ((bi & 31) == lane) used |= 1u << (bi >> 5);
                if (lane == 0) cand[it] = bi;
            }
        } else if (w == 1) {
            // target-loss log-softmax for row b (warp 1 alone)
            float v[7];
            float mx = -1e30f;
            #pragma unroll
            for (int k = 0; k < 7; k++) {
                int p = lane + 32 * k;
                v[k] = (p < NCLSn) ? tlog[b * NCLSn + p] : -1e30f;
                mx = fmaxf(mx, v[k]);
            }
            #pragma unroll
            for (int off = 16; off; off >>= 1)
                mx = fmaxf(mx, __shfl_xor_sync(0xffffffffu, mx, off));
            float se = 0.f;
            #pragma unroll
            for (int k = 0; k < 7; k++) {
                int p = lane + 32 * k;
                if (p < NCLSn) se += expf(v[k] - mx);
            }
            #pragma unroll
            for (int off = 16; off; off >>= 1)
                se += __shfl_xor_sync(0xffffffffu, se, off);
            if (lane == 0) {
                int cls = tt[b];
                g_tl[b] = -(tlog[b * NCLSn + cls] - mx - logf(se));
            }
        } else if (w == 2) {
            // l1 partial slice [b*175, b*175+175)
            float lp = 0.f;
            int base = b * 175;
            #pragma unroll
            for (int k = 0; k < 6; k++) {
                int i = lane + 32 * k;
                if (i < 175) lp += fabsf(wgt[base + i] * msk[base + i]);
            }
            #pragma unroll
            for (int off = 16; off; off >>= 1)
                lp += __shfl_down_sync(0xffffffffu, lp, off);
            if (lane == 0) g_l1[b] = lp;
        }
        __syncthreads();

        // clst/sep per concept (threads 0..111)
        float m1s = 0.f, m2s = 0.f;
        if (t < Cn) {
            float yv = cy[b * Cn + t];
            int r1 = (yv > 0.5f) ? t : t + Cn;
            int r2 = (yv > 0.5f) ? t + Cn : t;
            float m1 = 1e30f;
            const int* gi = g_idx[r1];
            #pragma unroll
            for (int k = 0; k < 10; k++) m1 = fminf(m1, md[gi[k]]);
            unsigned long long mw0 = g_mask[r2][0], mw1 = g_mask[r2][1];
            unsigned long long mw2 = g_mask[r2][2], mw3 = g_mask[r2][3];
            float m2 = 1e30f;
            #pragma unroll
            for (int k = 0; k < 11; k++) {
                int id = cand[k];
                unsigned long long wsel = (id < 64) ? mw0 : (id < 128) ? mw1
                                        : (id < 192) ? mw2 : mw3;
                if (!((wsel >> (id & 63)) & 1ull)) { m2 = md[id]; break; }
            }
            m1s = m1; m2s = m2;
        }
        #pragma unroll
        for (int off = 16; off; off >>= 1) {
            m1s += __shfl_down_sync(0xffffffffu, m1s, off);
            m2s += __shfl_down_sync(0xffffffffu, m2s, off);
        }
        if (lane == 0) { sm1[w] = m1s; sm2[w] = m2s; }
        __syncthreads();
        if (t == 0) {
            g_clst[b] = sm1[0] + sm1[1] + sm1[2] + sm1[3];
            g_sep[b]  = sm2[0] + sm2[1] + sm2[2] + sm2[3];
        }
    } else {
        // per-concept block: BCE column sum + ortho_c dot
        const int c = bid - Bn;
        float x0 = cx[t * Cn + c], y0 = cy[t * Cn + c];
        float bce = fmaxf(x0, 0.f) + log1pf(expf(-fabsf(x0))) - x0 * y0;
        float x1 = cx[(t + 128) * Cn + c], y1 = cy[(t + 128) * Cn + c];
        bce += fmaxf(x1, 0.f) + log1pf(expf(-fabsf(x1))) - x1 * y1;

        float oc = g_ua[c * Pn + t] * g_ua[(c + Cn) * Pn + t];
        if (t < Pn - 128)
            oc += g_ua[c * Pn + 128 + t] * g_ua[(c + Cn) * Pn + 128 + t];

        #pragma unroll
        for (int off = 16; off; off >>= 1) {
            bce += __shfl_down_sync(0xffffffffu, bce, off);
            oc  += __shfl_down_sync(0xffffffffu, oc, off);
        }
        if (lane == 0) { sm1[w] = bce; sm2[w] = oc; }
        __syncthreads();
        if (t == 0) {
            float bs = sm1[0] + sm1[1] + sm1[2] + sm1[3];
            out[1 + c] = bs / (float)Bn;
            g_part_ent[c] = bs;
            g_oc[c] = sm2[0] + sm2[1] + sm2[2] + sm2[3];
        }
    }

    // ---- last-block final scalar reduction ----
    __threadfence();
    if (t == 0) amLast = (atomicAdd(&g_ctr, 1) == (Bn + Cn - 1));
    __syncthreads();
    if (amLast) {
        float l1   = bsum128(g_l1[t]   + g_l1[t + 128], reds, t);
        float tls  = bsum128(g_tl[t]   + g_tl[t + 128], reds, t);
        float cls  = bsum128(g_clst[t] + g_clst[t + 128], reds, t);
        float sps  = bsum128(g_sep[t]  + g_sep[t + 128], reds, t);
        float ents = bsum128((t < Cn) ? g_part_ent[t] : 0.f, reds, t);
        float ops  = bsum128(g_aop[t] + ((t < C2 - 128) ? g_aop[t + 128] : 0.f), reds, t);
        float ocs  = bsum128((t < Cn) ? g_oc[t] : 0.f, reds, t);
        if (t == 0) {
            float target_loss = tls / (float)Bn;
            float entropy     = ents / (float)(Bn * Cn);
            float clst        = cls / (float)(Bn * Cn);
            float sep         = sps / (float)(Bn * Cn);
            float ortho_p     = ops / (float)(Dn * Cn * 2) - 1.0f;
            float ortho_c     = ocs / (float)(Dn * Cn);
            float summed = entropy + 0.8f * clst + (-0.08f) * sep
                         + 1e-4f * l1 + ortho_p + ortho_c;
            out[0]   = target_loss;
            out[113] = summed;
            out[114] = target_loss + summed;
            out[115] = entropy;
            out[116] = clst;
            out[117] = sep;
            out[118] = l1;
            out[119] = ortho_p;
            out[120] = ortho_c;
        }
    }
}

// ---------------------------------------------------------------------------
extern "C" void kernel_launch(void* const* d_in, const int* in_sizes, int n_in,
                              void* d_out, int out_size) {
    const float* cx    = (const float*)d_in[0];
    const float* cy    = (const float*)d_in[1];
    const float* mind  = (const float*)d_in[2];
    const float* proto = (const float*)d_in[3];
    const float* tlog  = (const float*)d_in[4];
    const int*   tt    = (const int*)d_in[5];
    const float* wgt   = (const float*)d_in[6];
    const float* msk   = (const float*)d_in[7];
    float* out = (float*)d_out;

    kA<<<C2, 128>>>(proto);
    kB<<<Bn + Cn, 128>>>(mind, cy, tlog, tt, wgt, msk, cx, out);
}

// round 5
// speedup vs baseline: 2.4151x; 1.2245x over previous
#include <cuda_runtime.h>
#include <math.h>

#define Bn    256
#define Cn    112
#define C2    224
#define Pn    200
#define Dn    10
#define NCLSn 200
#define NPROT 224
#define NB    (NPROT + Bn + Cn)   // 592 blocks

// ---------------- device scratch (fully rewritten every launch) -------------
__device__ unsigned long long g_mask[C2][4];
__device__ int   g_idx[C2][10];
__device__ float g_ua[C2 * Pn];
__device__ float g_aop[C2];
__device__ float g_oc[Cn];
__device__ float g_part_ent[Cn];
__device__ float g_clst[Bn];
__device__ float g_sep[Bn];
__device__ float g_tl[Bn];
__device__ float g_l1[Bn];
__device__ int   g_bar;    // proto-phase arrivals (reset by finale)
__device__ int   g_done;   // all-block completions (reset by finale)

// ---------------------------------------------------------------------------
// warp top-10 (largest, ties -> lower index) over Pn smem values. Warp 0 only.
__device__ __forceinline__ void topk10_row(const float* s, int r) {
    int lane = threadIdx.x & 31;
    float val[7];
    #pragma unroll
    for (int k = 0; k < 7; k++) {
        int p = lane + 32 * k;
        val[k] = (p < Pn) ? s[p] : -1e30f;
    }
    unsigned used = 0;
    unsigned long long mask[4] = {0ull, 0ull, 0ull, 0ull};
    #pragma unroll
    for (int it = 0; it < 10; it++) {
        float bv = -1e30f; int bi = 1 << 30;
        #pragma unroll
        for (int k = 0; k < 7; k++) {
            if (!((used >> k) & 1u)) {
                float x = val[k]; int p = lane + 32 * k;
                if (x > bv || (x == bv && p < bi)) { bv = x; bi = p; }
            }
        }
        #pragma unroll
        for (int off = 16; off; off >>= 1) {
            float ov = __shfl_down_sync(0xffffffffu, bv, off);
            int   oi = __shfl_down_sync(0xffffffffu, bi, off);
            if (ov > bv || (ov == bv && oi < bi)) { bv = ov; bi = oi; }
        }
        bi = __shfl_sync(0xffffffffu, bi, 0);
        if ((bi & 31) == lane) used |= 1u << (bi >> 5);
        if (lane == 0) { mask[bi >> 6] |= 1ull << (bi & 63); g_idx[r][it] = bi; }
    }
    if (lane == 0) {
        #pragma unroll
        for (int w = 0; w < 4; w++) g_mask[r][w] = mask[w];
    }
}

__device__ __forceinline__ float bsum128(float v, float* s, int t) {
    #pragma unroll
    for (int off = 16; off; off >>= 1) v += __shfl_down_sync(0xffffffffu, v, off);
    __syncthreads();
    if ((t & 31) == 0) s[t >> 5] = v;
    __syncthreads();
    return s[0] + s[1] + s[2] + s[3];
}

// acquire-spin until proto phase is published
__device__ __forceinline__ void wait_proto(int t) {
    if (t == 0) {
        while (*((volatile int*)&g_bar) < NPROT) __nanosleep(40);
    }
    __syncthreads();
    __threadfence();
}

// ---------------------------------------------------------------------------
__global__ __launch_bounds__(128) void fused(const float* __restrict__ proto,
                                             const float* __restrict__ mind,
                                             const float* __restrict__ cy,
                                             const float* __restrict__ tlog,
                                             const int* __restrict__ tt,
                                             const float* __restrict__ wgt,
                                             const float* __restrict__ msk,
                                             const float* __restrict__ cx,
                                             float* __restrict__ out) {
    __shared__ float sh[Pn * Dn];      // proto tile / reused nowhere else
    __shared__ float sA[Pn];           // rowsums / md
    __shared__ float aux[128];         // part[100] / cy cache
    __shared__ float invn[Dn];
    __shared__ float redw[4], redw2[4];
    __shared__ int   cand[11];
    __shared__ int   amLast;

    const int bid  = blockIdx.x;
    const int t    = threadIdx.x;
    const int lane = t & 31;
    const int w    = t >> 5;

    if (bid < NPROT) {
        // =================== proto-row block (r = bid) ======================
        const int r = bid;
        const float4* pr = (const float4*)(proto + (size_t)r * Pn * Dn);
        #pragma unroll
        for (int i = t; i < (Pn * Dn) / 4; i += 128) ((float4*)sh)[i] = pr[i];
        __syncthreads();

        {   // row sums
            float a = 0.f;
            #pragma unroll
            for (int d = 0; d < Dn; d++) a += sh[t * Dn + d];
            sA[t] = a;
            int p2 = t + 128;
            if (p2 < Pn) {
                float b = 0.f;
                #pragma unroll
                for (int d = 0; d < Dn; d++) b += sh[p2 * Dn + d];
                sA[p2] = b;
            }
        }
        if (t < 100) {   // column sq-norm partials
            int d = t / 10, seg = t % 10;
            float s = 0.f;
            #pragma unroll
            for (int p = seg * 20; p < seg * 20 + 20; p++) {
                float v = sh[p * Dn + d]; s += v * v;
            }
            aux[t] = s;
        }
        __syncthreads();
        if (t < Dn) {
            float s = 0.f;
            #pragma unroll
            for (int seg = 0; seg < 10; seg++) s += aux[t * 10 + seg];
            invn[t] = rsqrtf(fmaxf(s, 1e-16f));
        }
        __syncthreads();

        float aop = 0.f;
        if (t < 32) {
            topk10_row(sA, r);
        } else {
            for (int p = t - 32; p < Pn; p += 96) {
                float ua = 0.f;
                #pragma unroll
                for (int d = 0; d < Dn; d++) ua += sh[p * Dn + d] * invn[d];
                g_ua[r * Pn + p] = ua;
                aop += ua * ua;
            }
            #pragma unroll
            for (int off = 16; off; off >>= 1)
                aop += __shfl_down_sync(0xffffffffu, aop, off);
            if (lane == 0) redw[w] = aop;
        }
        __syncthreads();
        if (t == 0) g_aop[r] = redw[1] + redw[2] + redw[3];

        // publish
        __threadfence();
        if (t == 0) atomicAdd(&g_bar, 1);

    } else if (bid < NPROT + Bn) {
        // =================== per-batch block (b) ============================
        const int b = bid - NPROT;
        sA[t] = mind[b * Pn + t];
        if (t < Pn - 128) sA[t + 128] = mind[b * Pn + 128 + t];
        if (t < Cn) aux[t] = cy[b * Cn + t];     // prefetch cy row
        __syncthreads();

        if (w == 0) {
            // 11 smallest of md -> cand
            float val[7];
            #pragma unroll
            for (int k = 0; k < 7; k++) {
                int p = lane + 32 * k;
                val[k] = (p < Pn) ? sA[p] : 1e30f;
            }
            unsigned used = 0;
            #pragma unroll
            for (int it = 0; it < 11; it++) {
                float bv = 1e30f; int bi = 1 << 30;
                #pragma unroll
                for (int k = 0; k < 7; k++) {
                    if (!((used >> k) & 1u)) {
                        float xv = val[k]; int p = lane + 32 * k;
                        if (xv < bv || (xv == bv && p < bi)) { bv = xv; bi = p; }
                    }
                }
                #pragma unroll
                for (int off = 16; off; off >>= 1) {
                    float ov = __shfl_down_sync(0xffffffffu, bv, off);
                    int   oi = __shfl_down_sync(0xffffffffu, bi, off);
                    if (ov < bv || (ov == bv && oi < bi)) { bv = ov; bi = oi; }
                }
                bi = __shfl_sync(0xffffffffu, bi, 0);
                if ((bi & 31) == lane) used |= 1u << (bi >> 5);
                if (lane == 0) cand[it] = bi;
            }
        } else if (w == 1) {
            // log-softmax target loss
            float v[7];
            float mx = -1e30f;
            #pragma unroll
            for (int k = 0; k < 7; k++) {
                int p = lane + 32 * k;
                v[k] = (p < NCLSn) ? tlog[b * NCLSn + p] : -1e30f;
                mx = fmaxf(mx, v[k]);
            }
            #pragma unroll
            for (int off = 16; off; off >>= 1)
                mx = fmaxf(mx, __shfl_xor_sync(0xffffffffu, mx, off));
            float se = 0.f;
            #pragma unroll
            for (int k = 0; k < 7; k++) {
                int p = lane + 32 * k;
                if (p < NCLSn) se += expf(v[k] - mx);
            }
            #pragma unroll
            for (int off = 16; off; off >>= 1)
                se += __shfl_xor_sync(0xffffffffu, se, off);
            if (lane == 0) {
                int cls = tt[b];
                g_tl[b] = -(tlog[b * NCLSn + cls] - mx - logf(se));
            }
        } else if (w == 2) {
            // l1 slice [b*175, b*175+175)
            float lp = 0.f;
            int base = b * 175;
            #pragma unroll
            for (int k = 0; k < 6; k++) {
                int i = lane + 32 * k;
                if (i < 175) lp += fabsf(wgt[base + i] * msk[base + i]);
            }
            #pragma unroll
            for (int off = 16; off; off >>= 1)
                lp += __shfl_down_sync(0xffffffffu, lp, off);
            if (lane == 0) g_l1[b] = lp;
        }

        // wait for proto masks, then clst/sep
        wait_proto(t);

        float m1s = 0.f, m2s = 0.f;
        if (t < Cn) {
            float yv = aux[t];
            int r1 = (yv > 0.5f) ? t : t + Cn;
            int r2 = (yv > 0.5f) ? t + Cn : t;
            float m1 = 1e30f;
            const int* gi = g_idx[r1];
            #pragma unroll
            for (int k = 0; k < 10; k++) m1 = fminf(m1, sA[gi[k]]);
            unsigned long long mw0 = g_mask[r2][0], mw1 = g_mask[r2][1];
            unsigned long long mw2 = g_mask[r2][2], mw3 = g_mask[r2][3];
            float m2 = 1e30f;
            #pragma unroll
            for (int k = 0; k < 11; k++) {
                int id = cand[k];
                unsigned long long wsel = (id < 64) ? mw0 : (id < 128) ? mw1
                                        : (id < 192) ? mw2 : mw3;
                if (!((wsel >> (id & 63)) & 1ull)) { m2 = sA[id]; break; }
            }
            m1s = m1; m2s = m2;
        }
        #pragma unroll
        for (int off = 16; off; off >>= 1) {
            m1s += __shfl_down_sync(0xffffffffu, m1s, off);
            m2s += __shfl_down_sync(0xffffffffu, m2s, off);
        }
        if (lane == 0) { redw[w] = m1s; redw2[w] = m2s; }
        __syncthreads();
        if (t == 0) {
            g_clst[b] = redw[0] + redw[1] + redw[2] + redw[3];
            g_sep[b]  = redw2[0] + redw2[1] + redw2[2] + redw2[3];
        }

    } else {
        // =================== per-concept block (c) ==========================
        const int c = bid - NPROT - Bn;
        float x0 = cx[t * Cn + c], y0 = cy[t * Cn + c];
        float bce = fmaxf(x0, 0.f) + log1pf(expf(-fabsf(x0))) - x0 * y0;
        float x1 = cx[(t + 128) * Cn + c], y1 = cy[(t + 128) * Cn + c];
        bce += fmaxf(x1, 0.f) + log1pf(expf(-fabsf(x1))) - x1 * y1;
        #pragma unroll
        for (int off = 16; off; off >>= 1)
            bce += __shfl_down_sync(0xffffffffu, bce, off);
        if (lane == 0) redw[w] = bce;
        __syncthreads();
        if (t == 0) {
            float bs = redw[0] + redw[1] + redw[2] + redw[3];
            out[1 + c] = bs / (float)Bn;
            g_part_ent[c] = bs;
        }

        // wait for g_ua, then ortho_c dot
        wait_proto(t);

        float oc = g_ua[c * Pn + t] * g_ua[(c + Cn) * Pn + t];
        if (t < Pn - 128)
            oc += g_ua[c * Pn + 128 + t] * g_ua[(c + Cn) * Pn + 128 + t];
        #pragma unroll
        for (int off = 16; off; off >>= 1)
            oc += __shfl_down_sync(0xffffffffu, oc, off);
        if (lane == 0) redw2[w] = oc;
        __syncthreads();
        if (t == 0) g_oc[c] = redw2[0] + redw2[1] + redw2[2] + redw2[3];
    }

    // =================== last-block finale ==================================
    __threadfence();
    if (t == 0) amLast = (atomicAdd(&g_done, 1) == NB - 1);
    __syncthreads();
    if (amLast) {
        float l1   = bsum128(g_l1[t]   + g_l1[t + 128], redw, t);
        float tls  = bsum128(g_tl[t]   + g_tl[t + 128], redw, t);
        float cls  = bsum128(g_clst[t] + g_clst[t + 128], redw, t);
        float sps  = bsum128(g_sep[t]  + g_sep[t + 128], redw, t);
        float ents = bsum128((t < Cn) ? g_part_ent[t] : 0.f, redw, t);
        float ops  = bsum128(g_aop[t] + ((t < C2 - 128) ? g_aop[t + 128] : 0.f), redw, t);
        float ocs  = bsum128((t < Cn) ? g_oc[t] : 0.f, redw, t);
        if (t == 0) {
            float target_loss = tls / (float)Bn;
            float entropy     = ents / (float)(Bn * Cn);
            float clst        = cls / (float)(Bn * Cn);
            float sep         = sps / (float)(Bn * Cn);
            float ortho_p     = ops / (float)(Dn * Cn * 2) - 1.0f;
            float ortho_c     = ocs / (float)(Dn * Cn);
            float summed = entropy + 0.8f * clst + (-0.08f) * sep
                         + 1e-4f * l1 + ortho_p + ortho_c;
            out[0]   = target_loss;
            out[113] = summed;
            out[114] = target_loss + summed;
            out[115] = entropy;
            out[116] = clst;
            out[117] = sep;
            out[118] = l1;
            out[119] = ortho_p;
            out[120] = ortho_c;
            // reset counters for next graph replay (we are provably last)
            g_bar  = 0;
            g_done = 0;
        }
    }
}

// ---------------------------------------------------------------------------
extern "C" void kernel_launch(void* const* d_in, const int* in_sizes, int n_in,
                              void* d_out, int out_size) {
    const float* cx    = (const float*)d_in[0];
    const float* cy    = (const float*)d_in[1];
    const float* mind  = (const float*)d_in[2];
    const float* proto = (const float*)d_in[3];
    const float* tlog  = (const float*)d_in[4];
    const int*   tt    = (const int*)d_in[5];
    const float* wgt   = (const float*)d_in[6];
    const float* msk   = (const float*)d_in[7];
    float* out = (float*)d_out;

    fused<<<NB, 128>>>(proto, mind, cy, tlog, tt, wgt, msk, cx, out);
}